// round 4
// baseline (speedup 1.0000x reference)
#include <cuda_runtime.h>
#include <math.h>

// Fused block-DCT + soft-histogram, v4: high-occupancy k-split + vectorized
// input reads.
//
// Grid (16 batch, 32 block-rows, 2 k-halves) = 1024 CTAs x 256 threads.
// Thread = (blk = lane, 4 consecutive k). Input staged in smem as
// [blk][p] with stride 68 (conflict-free float4 reads over p). Per-output
// DCT sum is the same ascending-p FMA chain as v1-v3 (bit-identical).
//
// Histogram: gamma=1e6 saturates sigmoids to exact 0/1 except within ~3e-5
// of an integer threshold -> hard count (+1/1024, exact dyadic), aggregated
// per warp via __match_any_sync into a single global atomicAdd per distinct
// bin. Rare soft-edge elements compute the boundary sigmoids exactly.

#define NBINS   120
#define INV1024 (1.0f / 1024.0f)
#define PSTRIDE 68   // words per block row in in_s; 68 % 32 == 4 -> conflict-free f4

__global__ void __launch_bounds__(256, 7)
dct_hist_kernel(const float* __restrict__ in,
                const float* __restrict__ basis,
                float* __restrict__ out)
{
    __shared__ float B_s[64 * 32];          // basis [p][kk] for this half, 8 KB
    __shared__ float in_s[32 * PSTRIDE];    // input [blk][p] pad 68, 8.5 KB

    const int b   = blockIdx.x;   // batch
    const int row = blockIdx.y;   // block-row 0..31
    const int kh  = blockIdx.z;   // k-half 0/1
    const int tid = threadIdx.x;

    // Load basis half: B_s[p*32 + kk] = basis[p*64 + kh*32 + kk] (coalesced)
    #pragma unroll
    for (int i = tid; i < 64 * 32; i += 256) {
        int p  = i >> 5;
        int kk = i & 31;
        B_s[i] = basis[(p << 6) + (kh << 5) + kk];
    }

    // Load input strip: 8 pixel rows x 256 cols -> in_s[blk][p], float4 stores
    const float4* src = reinterpret_cast<const float4*>(
        in + ((size_t)b * 256 + (size_t)row * 8) * 256);
    #pragma unroll
    for (int i = tid; i < 512; i += 256) {
        float4 v  = src[i];
        int r     = i >> 6;              // pixel row 0..7 (= dx)
        int c0    = (i & 63) << 2;       // col 0..252 step 4
        int blk   = c0 >> 3;             // 0..31
        int p     = (r << 3) | (c0 & 7); // p = dx*8 + dy, multiple of 4
        *reinterpret_cast<float4*>(&in_s[blk * PSTRIDE + p]) = v;
    }
    __syncthreads();

    // DCT: thread -> (blk = lane, 4 consecutive k at warp*4)
    const int lane = tid & 31;
    const int k0   = (tid >> 5) << 2;   // 0,4,...,28 (uniform per warp)

    float a0 = 0.f, a1 = 0.f, a2 = 0.f, a3 = 0.f;
    const float* arow = in_s + lane * PSTRIDE;
    #pragma unroll
    for (int q = 0; q < 16; q++) {
        float4 a = *reinterpret_cast<const float4*>(arow + (q << 2)); // 4 p's
        #pragma unroll
        for (int s = 0; s < 4; s++) {
            int p    = (q << 2) + s;
            float av = (s == 0) ? a.x : (s == 1) ? a.y : (s == 2) ? a.z : a.w;
            float4 qb = *reinterpret_cast<const float4*>(B_s + (p << 5) + k0);
            a0 += av * qb.x;  a1 += av * qb.y;
            a2 += av * qb.z;  a3 += av * qb.w;
        }
    }

    // Scatter: warp-aggregated global atomics
    float* outb = out + (size_t)b * NBINS * 64;
    float vals[4] = {a0, a1, a2, a3};

    #pragma unroll
    for (int j = 0; j < 4; j++) {
        float v  = vals[j];
        float fl = floorf(v);
        int   ti = (int)fl + 60;
        float d  = v - fl;
        const int kk = (kh << 5) + k0 + j;   // uniform per warp

        bool hard = (d > 3e-5f) && (d < 1.0f - 3e-5f);
        unsigned hard_mask = __ballot_sync(0xffffffffu, hard);

        if (hard) {
            unsigned grp = __match_any_sync(hard_mask, ti);
            int leader   = __ffs(grp) - 1;
            if (lane == leader && (unsigned)ti < (unsigned)NBINS) {
                float w = (float)__popc(grp) * INV1024;
                atomicAdd(&outb[ti * 64 + kk], w);
            }
        } else {
            // Soft edge: exact fp32 sigmoids at the two nearest thresholds.
            float z0 = 1e6f * (v - (float)(ti - 60));
            float z1 = 1e6f * (v - (float)(ti - 59));
            float s0 = (z0 >= 30.0f) ? 1.0f : (1.0f / (1.0f + expf(-z0)));
            float s1;
            if (z1 <= -30.0f) s1 = 0.0f;
            else { float e = expf(z1); s1 = e / (1.0f + e); }

            float w_lo  = (1.0f - s0) * INV1024;  // bin ti-1
            float w_mid = (s0 - s1)   * INV1024;  // bin ti
            float w_hi  = s1          * INV1024;  // bin ti+1
            if ((unsigned)(ti - 1) < (unsigned)NBINS && w_lo != 0.0f)
                atomicAdd(&outb[(ti - 1) * 64 + kk], w_lo);
            if ((unsigned)ti < (unsigned)NBINS && w_mid != 0.0f)
                atomicAdd(&outb[ti * 64 + kk], w_mid);
            if ((unsigned)(ti + 1) < (unsigned)NBINS && w_hi != 0.0f)
                atomicAdd(&outb[(ti + 1) * 64 + kk], w_hi);
        }
    }
}

extern "C" void kernel_launch(void* const* d_in, const int* in_sizes, int n_in,
                              void* d_out, int out_size)
{
    const float* in    = (const float*)d_in[0];   // [16,256,256,1]
    const float* basis = (const float*)d_in[1];   // [8,8,1,64]
    float* out = (float*)d_out;                   // [16,120,64,1]
    (void)in_sizes; (void)n_in;

    cudaMemsetAsync(d_out, 0, (size_t)out_size * sizeof(float), 0);

    dim3 grid(16, 32, 2);
    dct_hist_kernel<<<grid, 256>>>(in, basis, out);
}

// round 5
// speedup vs baseline: 1.0021x; 1.0021x over previous
#include <cuda_runtime.h>
#include <math.h>

// Fused block-DCT + soft-histogram, v5: packed f32x2 FMA + 128-thread CTAs.
//
// Grid (16 batch, 32 block-rows, 2 k-halves) = 1024 CTAs x 128 threads.
// Thread = (blk = lane, 8 consecutive k) held as 4 packed f32x2 accumulators.
// fma.rn.f32x2 computes two independent fma.rn.f32 -> each k's ascending-p
// accumulation chain is bit-identical to v1-v4 (rel_err ~6e-9 preserved).
//
// __launch_bounds__(128, 8): 8 CTAs/SM = 32 warps/SM (full occupancy) while
// still allowing 64 regs/thread for load pipelining - breaking the
// regs-vs-occupancy tradeoff that pinned v3/v4 at issue ~44%.
//
// Histogram: gamma=1e6 saturates sigmoids to exact 0/1 except within ~3e-5 of
// an integer threshold -> hard count (+1/1024, exact dyadic), warp-aggregated
// via __match_any_sync into one global atomicAdd per distinct bin.

#define NBINS   120
#define INV1024 (1.0f / 1024.0f)
#define PSTRIDE 68   // 68 % 32 == 4 -> conflict-free float4 reads over p

#define FMA_F32X2(d, a, b, c) \
    asm("fma.rn.f32x2 %0, %1, %2, %3;" \
        : "=l"(d) : "l"(a), "l"(b), "l"(c))

#define PACK_DUP_F32X2(d, f) \
    asm("mov.b64 %0, {%1, %1};" : "=l"(d) : "r"(__float_as_uint(f)))

__global__ void __launch_bounds__(128, 8)
dct_hist_kernel(const float* __restrict__ in,
                const float* __restrict__ basis,
                float* __restrict__ out)
{
    __shared__ __align__(16) float B_s[64 * 32];       // basis [p][kk], 8 KB
    __shared__ __align__(16) float in_s[32 * PSTRIDE]; // input [blk][p], 8.7 KB

    const int b   = blockIdx.x;   // batch
    const int row = blockIdx.y;   // block-row 0..31
    const int kh  = blockIdx.z;   // k-half 0/1
    const int tid = threadIdx.x;

    // Load basis half: B_s[p*32 + kk] = basis[p*64 + kh*32 + kk] (coalesced)
    #pragma unroll
    for (int i = tid; i < 64 * 32; i += 128) {
        int p  = i >> 5;
        int kk = i & 31;
        B_s[i] = basis[(p << 6) + (kh << 5) + kk];
    }

    // Load input strip: 8 pixel rows x 256 cols -> in_s[blk][p]
    const float4* src = reinterpret_cast<const float4*>(
        in + ((size_t)b * 256 + (size_t)row * 8) * 256);
    #pragma unroll
    for (int i = tid; i < 512; i += 128) {
        float4 v  = src[i];
        int r     = i >> 6;              // pixel row 0..7 (= dx)
        int c0    = (i & 63) << 2;       // col 0..252 step 4
        int blk   = c0 >> 3;             // 0..31
        int p     = (r << 3) | (c0 & 7); // p = dx*8 + dy, multiple of 4
        *reinterpret_cast<float4*>(&in_s[blk * PSTRIDE + p]) = v;
    }
    __syncthreads();

    // DCT: thread -> (blk = lane, 8 consecutive k at warp*8)
    const int lane = tid & 31;
    const int k0   = (tid >> 5) << 3;   // 0,8,16,24 (uniform per warp)

    unsigned long long acc0 = 0ull, acc1 = 0ull, acc2 = 0ull, acc3 = 0ull;
    const float* arow = in_s + lane * PSTRIDE;

    #pragma unroll
    for (int q = 0; q < 16; q++) {
        float4 a = *reinterpret_cast<const float4*>(arow + (q << 2)); // 4 p's
        #pragma unroll
        for (int s = 0; s < 4; s++) {
            int p    = (q << 2) + s;
            float av = (s == 0) ? a.x : (s == 1) ? a.y : (s == 2) ? a.z : a.w;
            unsigned long long av2;
            PACK_DUP_F32X2(av2, av);
            const ulonglong2* bp =
                reinterpret_cast<const ulonglong2*>(B_s + (p << 5) + k0);
            ulonglong2 b01 = bp[0];   // k0..k0+3 (two packed pairs)
            ulonglong2 b23 = bp[1];   // k0+4..k0+7
            FMA_F32X2(acc0, av2, b01.x, acc0);
            FMA_F32X2(acc1, av2, b01.y, acc1);
            FMA_F32X2(acc2, av2, b23.x, acc2);
            FMA_F32X2(acc3, av2, b23.y, acc3);
        }
    }

    // Unpack the 8 per-k results
    float vals[8];
    {
        unsigned lo, hi;
        asm("mov.b64 {%0, %1}, %2;" : "=r"(lo), "=r"(hi) : "l"(acc0));
        vals[0] = __uint_as_float(lo); vals[1] = __uint_as_float(hi);
        asm("mov.b64 {%0, %1}, %2;" : "=r"(lo), "=r"(hi) : "l"(acc1));
        vals[2] = __uint_as_float(lo); vals[3] = __uint_as_float(hi);
        asm("mov.b64 {%0, %1}, %2;" : "=r"(lo), "=r"(hi) : "l"(acc2));
        vals[4] = __uint_as_float(lo); vals[5] = __uint_as_float(hi);
        asm("mov.b64 {%0, %1}, %2;" : "=r"(lo), "=r"(hi) : "l"(acc3));
        vals[6] = __uint_as_float(lo); vals[7] = __uint_as_float(hi);
    }

    // Scatter: warp-aggregated global atomics
    float* outb = out + (size_t)b * NBINS * 64;

    #pragma unroll
    for (int j = 0; j < 8; j++) {
        float v  = vals[j];
        float fl = floorf(v);
        int   ti = (int)fl + 60;
        float d  = v - fl;
        const int kk = (kh << 5) + k0 + j;   // uniform per warp

        bool hard = (d > 3e-5f) && (d < 1.0f - 3e-5f);
        unsigned hard_mask = __ballot_sync(0xffffffffu, hard);

        if (hard) {
            unsigned grp = __match_any_sync(hard_mask, ti);
            int leader   = __ffs(grp) - 1;
            if (lane == leader && (unsigned)ti < (unsigned)NBINS) {
                float w = (float)__popc(grp) * INV1024;
                atomicAdd(&outb[ti * 64 + kk], w);
            }
        } else {
            // Soft edge: exact fp32 sigmoids at the two nearest thresholds.
            float z0 = 1e6f * (v - (float)(ti - 60));
            float z1 = 1e6f * (v - (float)(ti - 59));
            float s0 = (z0 >= 30.0f) ? 1.0f : (1.0f / (1.0f + expf(-z0)));
            float s1;
            if (z1 <= -30.0f) s1 = 0.0f;
            else { float e = expf(z1); s1 = e / (1.0f + e); }

            float w_lo  = (1.0f - s0) * INV1024;  // bin ti-1
            float w_mid = (s0 - s1)   * INV1024;  // bin ti
            float w_hi  = s1          * INV1024;  // bin ti+1
            if ((unsigned)(ti - 1) < (unsigned)NBINS && w_lo != 0.0f)
                atomicAdd(&outb[(ti - 1) * 64 + kk], w_lo);
            if ((unsigned)ti < (unsigned)NBINS && w_mid != 0.0f)
                atomicAdd(&outb[ti * 64 + kk], w_mid);
            if ((unsigned)(ti + 1) < (unsigned)NBINS && w_hi != 0.0f)
                atomicAdd(&outb[(ti + 1) * 64 + kk], w_hi);
        }
    }
}

extern "C" void kernel_launch(void* const* d_in, const int* in_sizes, int n_in,
                              void* d_out, int out_size)
{
    const float* in    = (const float*)d_in[0];   // [16,256,256,1]
    const float* basis = (const float*)d_in[1];   // [8,8,1,64]
    float* out = (float*)d_out;                   // [16,120,64,1]
    (void)in_sizes; (void)n_in;

    cudaMemsetAsync(d_out, 0, (size_t)out_size * sizeof(float), 0);

    dim3 grid(16, 32, 2);
    dct_hist_kernel<<<grid, 128>>>(in, basis, out);
}